// round 1
// baseline (speedup 1.0000x reference)
#include <cuda_runtime.h>
#include <math.h>

#define NB 256
#define TT 64
#define DD 1024
#define HH 1024
#define GG 4096
#define LL 16

// ---------------- scratch (device globals; no allocations allowed) -------------
__device__ float g_XW[NB * TT * GG];     // x @ Wx + b, per (n,t): 268 MB
__device__ float g_P[NB * LL * GG];      // P[n,l,:] = A_flat[n,:,l] @ Wattn: 64 MB
__device__ float g_AT[NB * LL * HH];     // A transposed to (n,l,h): 16 MB
__device__ float g_hA[NB * HH];          // h ping
__device__ float g_hB[NB * HH];          // h pong
__device__ float g_c[NB * HH];           // cell state
__device__ float g_attnZ[NB * GG];       // per-step: XW[:,t,:] + sum_l w_l P[n,l,:]

// ---------------- init: transpose A, compute h0 = mean, c0 = h0 ---------------
__global__ void init_kernel(const float* __restrict__ A) {
    int idx = blockIdx.x * blockDim.x + threadIdx.x;   // n*H + h
    int n = idx >> 10, h = idx & 1023;
    const float4* a4 = reinterpret_cast<const float4*>(A + (size_t)(n * HH + h) * 16);
    float s = 0.f;
#pragma unroll
    for (int q = 0; q < 4; q++) {
        float4 v = a4[q];
        g_AT[(size_t)(n * LL + q * 4 + 0) * HH + h] = v.x;
        g_AT[(size_t)(n * LL + q * 4 + 1) * HH + h] = v.y;
        g_AT[(size_t)(n * LL + q * 4 + 2) * HH + h] = v.z;
        g_AT[(size_t)(n * LL + q * 4 + 3) * HH + h] = v.w;
        s += v.x + v.y + v.z + v.w;
    }
    float h0 = s * (1.0f / 16.0f);
    g_hA[idx] = h0;
    g_c[idx] = h0;
}

// ---------------- generic 128x128x16 double-buffered SGEMM --------------------
// C[m, j] = sum_k Amat[m, k] * Bmat[k, j] (+ bias[j])
// grid.x = M/128, grid.y = Ncols/128, 256 threads, 8x8 microtile.
template <bool BIAS>
__global__ __launch_bounds__(256)
void sgemm128(const float* __restrict__ Ag0, const float* __restrict__ Bg0,
              const float* __restrict__ bias, float* __restrict__ C,
              int K, int Ncols) {
    __shared__ __align__(16) float As[2][16][132];   // padded (bank spread), rows 16B-aligned
    __shared__ __align__(16) float Bs[2][16][128];

    const int tid = threadIdx.x;
    const int m0 = blockIdx.x * 128, n0 = blockIdx.y * 128;
    const int trow = tid >> 4, tcol = tid & 15;
    const int ar = tid >> 2, ak = (tid & 3) * 4;     // A-tile: 128x16 = 512 f4, 2/thread
    const int bk = tid >> 5, bc = (tid & 31) * 4;    // B-tile: 16x128 = 512 f4, 2/thread
    const float* Ag = Ag0 + (size_t)m0 * K;
    const float* Bg = Bg0 + n0;

    float acc[8][8];
#pragma unroll
    for (int i = 0; i < 8; i++)
#pragma unroll
        for (int j = 0; j < 8; j++) acc[i][j] = 0.f;

    float4 pa0, pa1, pb0, pb1;
    pa0 = *(const float4*)(Ag + (size_t)ar * K + ak);
    pa1 = *(const float4*)(Ag + (size_t)(ar + 64) * K + ak);
    pb0 = *(const float4*)(Bg + (size_t)bk * Ncols + bc);
    pb1 = *(const float4*)(Bg + (size_t)(bk + 8) * Ncols + bc);

    As[0][ak + 0][ar] = pa0.x; As[0][ak + 1][ar] = pa0.y;
    As[0][ak + 2][ar] = pa0.z; As[0][ak + 3][ar] = pa0.w;
    As[0][ak + 0][ar + 64] = pa1.x; As[0][ak + 1][ar + 64] = pa1.y;
    As[0][ak + 2][ar + 64] = pa1.z; As[0][ak + 3][ar + 64] = pa1.w;
    *(float4*)&Bs[0][bk][bc] = pb0;
    *(float4*)&Bs[0][bk + 8][bc] = pb1;
    __syncthreads();

    int buf = 0;
    const int KT = K >> 4;
    for (int kt = 0; kt < KT; kt++) {
        if (kt + 1 < KT) {
            const float* Agk = Ag + ((kt + 1) << 4);
            const float* Bgk = Bg + (size_t)((kt + 1) << 4) * Ncols;
            pa0 = *(const float4*)(Agk + (size_t)ar * K + ak);
            pa1 = *(const float4*)(Agk + (size_t)(ar + 64) * K + ak);
            pb0 = *(const float4*)(Bgk + (size_t)bk * Ncols + bc);
            pb1 = *(const float4*)(Bgk + (size_t)(bk + 8) * Ncols + bc);
        }
#pragma unroll
        for (int k = 0; k < 16; k++) {
            float ra[8], rb[8];
            *(float4*)(ra)     = *(const float4*)&As[buf][k][trow * 8];
            *(float4*)(ra + 4) = *(const float4*)&As[buf][k][trow * 8 + 4];
            *(float4*)(rb)     = *(const float4*)&Bs[buf][k][tcol * 8];
            *(float4*)(rb + 4) = *(const float4*)&Bs[buf][k][tcol * 8 + 4];
#pragma unroll
            for (int i = 0; i < 8; i++)
#pragma unroll
                for (int j = 0; j < 8; j++) acc[i][j] += ra[i] * rb[j];
        }
        if (kt + 1 < KT) {
            int nb = buf ^ 1;
            As[nb][ak + 0][ar] = pa0.x; As[nb][ak + 1][ar] = pa0.y;
            As[nb][ak + 2][ar] = pa0.z; As[nb][ak + 3][ar] = pa0.w;
            As[nb][ak + 0][ar + 64] = pa1.x; As[nb][ak + 1][ar + 64] = pa1.y;
            As[nb][ak + 2][ar + 64] = pa1.z; As[nb][ak + 3][ar + 64] = pa1.w;
            *(float4*)&Bs[nb][bk][bc] = pb0;
            *(float4*)&Bs[nb][bk + 8][bc] = pb1;
            __syncthreads();
            buf = nb;
        }
    }

#pragma unroll
    for (int i = 0; i < 8; i++) {
        size_t row = (size_t)(m0 + trow * 8 + i);
#pragma unroll
        for (int jq = 0; jq < 2; jq++) {
            float4 v;
            v.x = acc[i][jq * 4 + 0]; v.y = acc[i][jq * 4 + 1];
            v.z = acc[i][jq * 4 + 2]; v.w = acc[i][jq * 4 + 3];
            int cb = n0 + tcol * 8 + jq * 4;
            if (BIAS) {
                v.x += bias[cb]; v.y += bias[cb + 1];
                v.z += bias[cb + 2]; v.w += bias[cb + 3];
            }
            *(float4*)(C + row * Ncols + cb) = v;
        }
    }
}

// ---------------- per-step: scores -> softmax -> attnZ = XW + sum_l w_l P -----
__global__ __launch_bounds__(512)
void attn_kernel(int t) {
    const int n = blockIdx.x;
    const int tid = threadIdx.x;
    const int warp = tid >> 5, lane = tid & 31;
    __shared__ float sw[16];

    const float* hcur = (t & 1) ? g_hB : g_hA;
    const float* hp = hcur + (size_t)n * HH;
    const float* ap = g_AT + ((size_t)n * LL + warp) * HH;

    float acc = 0.f;
    for (int k = lane; k < HH; k += 32) acc += hp[k] * ap[k];
#pragma unroll
    for (int o = 16; o > 0; o >>= 1) acc += __shfl_xor_sync(0xffffffffu, acc, o);
    if (lane == 0) sw[warp] = acc * 0.03125f;   // 1/sqrt(1024)
    __syncthreads();

    if (warp == 0) {
        float s = (lane < 16) ? sw[lane] : -1e30f;
        float m = s;
#pragma unroll
        for (int o = 16; o > 0; o >>= 1) m = fmaxf(m, __shfl_xor_sync(0xffffffffu, m, o));
        float e = (lane < 16) ? expf(s - m) : 0.f;
        float tot = e;
#pragma unroll
        for (int o = 16; o > 0; o >>= 1) tot += __shfl_xor_sync(0xffffffffu, tot, o);
        if (lane < 16) sw[lane] = e / tot;
    }
    __syncthreads();

    float wl[16];
#pragma unroll
    for (int l = 0; l < 16; l++) wl[l] = sw[l];

    const float4* xw4 = (const float4*)(g_XW + ((size_t)n * TT + t) * GG);
    const float4* p4  = (const float4*)(g_P + (size_t)n * LL * GG);
    float4* oz4 = (float4*)(g_attnZ + (size_t)n * GG);
#pragma unroll
    for (int it = 0; it < 2; it++) {
        int c = tid + it * 512;            // GG/4 = 1024 float4s
        float4 a = xw4[c];
#pragma unroll
        for (int l = 0; l < 16; l++) {
            float4 pv = p4[(size_t)l * (GG / 4) + c];
            float w = wl[l];
            a.x += w * pv.x; a.y += w * pv.y; a.z += w * pv.z; a.w += w * pv.w;
        }
        oz4[c] = a;
    }
}

// ---------------- per-step: h@Wh GEMM + fused gates + state update ------------
// Block tile: 64 rows (n) x 4 gate-strips of 32 cols. Thread (ty,tx): 8 rows,
// one column jh = jj+tx in each of the 4 gate slices -> gates computed locally.
__global__ __launch_bounds__(256)
void step_kernel(const float* __restrict__ Wh, float* __restrict__ out, int t) {
    __shared__ __align__(16) float Hs[2][16][68];
    __shared__ __align__(16) float Ws[2][16][128];

    const int tid = threadIdx.x;
    const int ty = tid >> 5, tx = tid & 31;
    const int bn = blockIdx.x * 64;
    const int jj = blockIdx.y * 32;

    const float* hcur = (t & 1) ? g_hB : g_hA;
    float* hnxt = (t & 1) ? g_hA : g_hB;

    const int hr = tid >> 2, hk = (tid & 3) * 4;     // H-tile 64x16 = 256 f4, 1/thread
    const int wk = tid >> 5, wc = tid & 31;          // W-tile 16x128 = 512 f4, 2/thread
    const int ws = wc >> 3, wq = (wc & 7) * 4;
    const size_t wcol = (size_t)(ws * 1024 + jj + wq);
    const float* Hg = hcur + (size_t)bn * HH;

    float acc[8][4];
#pragma unroll
    for (int i = 0; i < 8; i++)
#pragma unroll
        for (int s = 0; s < 4; s++) acc[i][s] = 0.f;

    float4 ph, pw0, pw1;
    ph  = *(const float4*)(Hg + (size_t)hr * HH + hk);
    pw0 = *(const float4*)(Wh + (size_t)wk * GG + wcol);
    pw1 = *(const float4*)(Wh + (size_t)(wk + 8) * GG + wcol);
    Hs[0][hk + 0][hr] = ph.x; Hs[0][hk + 1][hr] = ph.y;
    Hs[0][hk + 2][hr] = ph.z; Hs[0][hk + 3][hr] = ph.w;
    *(float4*)&Ws[0][wk][wc * 4] = pw0;
    *(float4*)&Ws[0][wk + 8][wc * 4] = pw1;
    __syncthreads();

    int buf = 0;
    for (int kt = 0; kt < 64; kt++) {
        if (kt < 63) {
            int k0 = (kt + 1) * 16;
            ph  = *(const float4*)(Hg + (size_t)hr * HH + k0 + hk);
            pw0 = *(const float4*)(Wh + (size_t)(k0 + wk) * GG + wcol);
            pw1 = *(const float4*)(Wh + (size_t)(k0 + wk + 8) * GG + wcol);
        }
#pragma unroll
        for (int k = 0; k < 16; k++) {
            float ra[8];
            *(float4*)(ra)     = *(const float4*)&Hs[buf][k][ty * 8];
            *(float4*)(ra + 4) = *(const float4*)&Hs[buf][k][ty * 8 + 4];
            float rb0 = Ws[buf][k][tx];
            float rb1 = Ws[buf][k][32 + tx];
            float rb2 = Ws[buf][k][64 + tx];
            float rb3 = Ws[buf][k][96 + tx];
#pragma unroll
            for (int i = 0; i < 8; i++) {
                acc[i][0] += ra[i] * rb0;
                acc[i][1] += ra[i] * rb1;
                acc[i][2] += ra[i] * rb2;
                acc[i][3] += ra[i] * rb3;
            }
        }
        if (kt < 63) {
            int nb = buf ^ 1;
            Hs[nb][hk + 0][hr] = ph.x; Hs[nb][hk + 1][hr] = ph.y;
            Hs[nb][hk + 2][hr] = ph.z; Hs[nb][hk + 3][hr] = ph.w;
            *(float4*)&Ws[nb][wk][wc * 4] = pw0;
            *(float4*)&Ws[nb][wk + 8][wc * 4] = pw1;
            __syncthreads();
            buf = nb;
        }
    }

#pragma unroll
    for (int i = 0; i < 8; i++) {
        int n = bn + ty * 8 + i;
        int jh = jj + tx;
        size_t zb = (size_t)n * GG + jh;
        float a0 = acc[i][0] + g_attnZ[zb];
        float a1 = acc[i][1] + g_attnZ[zb + 1024];
        float a2 = acc[i][2] + g_attnZ[zb + 2048];
        float a3 = acc[i][3] + g_attnZ[zb + 3072];
        float gi = 1.f / (1.f + expf(-a0));
        float gf = 1.f / (1.f + expf(-a1));
        float go = 1.f / (1.f + expf(-a2));
        float gg = tanhf(a3);
        size_t hidx = (size_t)n * HH + jh;
        float cn = gf * g_c[hidx] + gi * gg;
        g_c[hidx] = cn;
        float hn = go * tanhf(cn);
        hnxt[hidx] = hn;
        out[((size_t)n * TT + t) * HH + jh] = hn;
    }
}

// ---------------- launch ------------------------------------------------------
extern "C" void kernel_launch(void* const* d_in, const int* in_sizes, int n_in,
                              void* d_out, int out_size) {
    const float* x     = (const float*)d_in[0];
    const float* A     = (const float*)d_in[1];
    const float* Wx    = (const float*)d_in[2];
    const float* Wh    = (const float*)d_in[3];
    const float* Wattn = (const float*)d_in[4];
    const float* b     = (const float*)d_in[5];
    float* out = (float*)d_out;

    float *p_xw, *p_p, *p_at;
    cudaGetSymbolAddress((void**)&p_xw, g_XW);
    cudaGetSymbolAddress((void**)&p_p, g_P);
    cudaGetSymbolAddress((void**)&p_at, g_AT);

    // Phase 0: transpose A, init h0/c0
    init_kernel<<<(NB * HH) / 256, 256>>>(A);

    // Phase 1a: XW[n*T+t, :] = x @ Wx + b   (M=16384, K=1024, N=4096)
    {
        dim3 g((NB * TT) / 128, GG / 128);
        sgemm128<true><<<g, 256>>>(x, Wx, b, p_xw, DD, GG);
    }
    // Phase 1b: P[n*16+l, :] = AT @ Wattn   (M=4096, K=1024, N=4096)
    {
        dim3 g((NB * LL) / 128, GG / 128);
        sgemm128<false><<<g, 256>>>(p_at, Wattn, nullptr, p_p, HH, GG);
    }

    // Phase 2: sequential scan over T
    for (int t = 0; t < TT; t++) {
        attn_kernel<<<NB, 512>>>(t);
        dim3 gs(NB / 64, HH / 32);
        step_kernel<<<gs, 256>>>(Wh, out, t);
    }
}